// round 12
// baseline (speedup 1.0000x reference)
#include <cuda_runtime.h>

// BasicRNN B=128, S=8000, H=64 — single fused kernel:
//  rec blocks (bid 0..127): recurrence, 64 active threads; stores h=tanh(z) to
//       scratch; publishes progress every 320 steps (fence + flag). After the
//       loop, the SAME block computes its batch's LAST readout chunk (ck=24),
//       waits for chunks 0..23 (done counter), does the deterministic
//       fixed-order final reduce -> out[b], and resets flags for graph replay.
//  readout blocks (bid 128..3199): poll progress, process chunks ck=0..23;
//       all their dependencies (t<=7680) are published DURING the recurrence,
//       so no post-recurrence drain remains.

#define BATCH 128
#define SEQ   8000
#define HID   64
#define CHUNK 1600
#define NCHUNK (SEQ / CHUNK)
#define PUB   320               // progress publish granularity (steps)
#define GROUPS (SEQ / 4)        // 2000 groups of 4 timesteps
#define NCHK2 25                // total partial slots per batch
#define RCHK  24                // chunks handled by readout blocks (0..23)
#define GCHK  (GROUPS / NCHK2)  // 80 groups per chunk (320 steps)
#define GWARP (GCHK / 8)        // 10 groups per warp (readout blocks)

typedef unsigned long long ull;

// h scratch: [B][GROUPS][HID][4] = 262 MB
__device__ float g_h[(size_t)BATCH * GROUPS * HID * 4];
__device__ float g_pnum[BATCH * NCHK2];
__device__ float g_pden[BATCH * NCHK2];
__device__ volatile unsigned g_prog[BATCH];   // steps completed per batch
__device__ unsigned g_done[BATCH];            // readout chunks completed (0..24)

__device__ __forceinline__ ull ffma2(ull a, ull b, ull c) {
    ull d;
    asm("fma.rn.f32x2 %0, %1, %2, %3;" : "=l"(d) : "l"(a), "l"(b), "l"(c));
    return d;
}
__device__ __forceinline__ ull fadd2(ull a, ull b) {
    ull d;
    asm("add.rn.f32x2 %0, %1, %2;" : "=l"(d) : "l"(a), "l"(b));
    return d;
}
__device__ __forceinline__ float lo32(ull a) { return __int_as_float((unsigned)a); }
__device__ __forceinline__ float hi32(ull a) { return __int_as_float((unsigned)(a >> 32)); }
__device__ __forceinline__ ull pack2(float lo, float hi) {
    return (ull)__float_as_uint(lo) | ((ull)__float_as_uint(hi) << 32);
}

__device__ __forceinline__ float tanh_hw(float z) {        // MUFU.TANH
    float r;
    asm("tanh.approx.f32 %0, %1;" : "=f"(r) : "f"(z));
    return r;
}
__device__ __forceinline__ float sigmoid_tanh(float x) {   // 1 MUFU
    return fmaf(0.5f, tanh_hw(0.5f * x), 0.5f);
}

// readout inner body: `gcount` groups from base; accumulates (num, den).
__device__ __forceinline__ void readout_groups(
    const float4* base, int gcount, int lane,
    float f0a, float f0b, float f1a, float f1b, float fb0, float fb1,
    float& num, float& den)
{
    #pragma unroll 2
    for (int i = 0; i < gcount; ++i) {
        const float4* hg = base + (size_t)i * HID;
        float4 hA = hg[lane];                // rows 0..31, 4 steps (tanh'd)
        float4 hB = hg[32 + lane];           // rows 32..63
        float p0[4], p1[4];
        p0[0] = fmaf(f0a, hA.x, f0b * hB.x); p1[0] = fmaf(f1a, hA.x, f1b * hB.x);
        p0[1] = fmaf(f0a, hA.y, f0b * hB.y); p1[1] = fmaf(f1a, hA.y, f1b * hB.y);
        p0[2] = fmaf(f0a, hA.z, f0b * hB.z); p1[2] = fmaf(f1a, hA.z, f1b * hB.z);
        p0[3] = fmaf(f0a, hA.w, f0b * hB.w); p1[3] = fmaf(f1a, hA.w, f1b * hB.w);
        #pragma unroll
        for (int o = 16; o > 0; o >>= 1) {
            #pragma unroll
            for (int j = 0; j < 4; j++) {
                p0[j] += __shfl_xor_sync(0xffffffffu, p0[j], o);
                p1[j] += __shfl_xor_sync(0xffffffffu, p1[j], o);
            }
        }
        #pragma unroll
        for (int j = 0; j < 4; j++) {
            float sel = sigmoid_tanh(p0[j] + fb0);
            float sc  = sigmoid_tanh(p1[j] + fb1);
            den += sel;
            num += sc * sel;
        }
    }
}

// ---------------- fused recurrence + overlapped readout + in-kernel finish ----------------
__global__ void __launch_bounds__(256, 1)
rnn_fused(const float* __restrict__ x,      // [B, S]
          const float* __restrict__ W_ih,   // [H, 1]
          const float* __restrict__ b_ih,   // [H]
          const float* __restrict__ W_hh,   // [H, H]
          const float* __restrict__ b_hh,   // [H]
          const float* __restrict__ fc_w,   // [2, H]
          const float* __restrict__ fc_b,   // [2]
          float* __restrict__ out)          // [B]
{
    const int bid = blockIdx.x;
    const int tid = threadIdx.x;

    if (bid < BATCH) {
        // ================= recurrence block =================
        if (tid >= 64) return;           // 64 active threads, 2 warps
        __shared__ __align__(16) float hb[2][HID];
        __shared__ float xs[CHUNK];
        __shared__ float snum2[2], sden2[2];

        const int b = bid;
        const int r = tid;               // row 0..63

        ull w2[32];                      // full W_hh row, packed f32x2
        {
            const double* wp = (const double*)(W_hh + r * HID);
            #pragma unroll
            for (int i = 0; i < 32; i++) w2[i] = __double_as_longlong(wp[i]);
        }
        const float wih_r  = W_ih[r];
        const float bias_r = b_ih[r] + b_hh[r];

        hb[0][r] = 0.0f;   // h_0

        const float* xb = x + (long)b * SEQ;
        float4* hp = (float4*)(g_h + (size_t)b * GROUPS * HID * 4) + r;

        __syncthreads();

        for (int c = 0; c < NCHUNK; ++c) {
            for (int i = r; i < CHUNK; i += 64)
                xs[i] = xb[c * CHUNK + i];
            __syncthreads();

            #pragma unroll 1
            for (int s = 0; s < CHUNK; s += 4) {
                float xp[4];
                #pragma unroll
                for (int u = 0; u < 4; ++u)
                    xp[u] = fmaf(xs[s + u], wih_r, bias_r);

                float hq[4];
                #pragma unroll
                for (int u = 0; u < 4; ++u) {
                    const float* hsrc = hb[u & 1];
                    float*       hdst = hb[(u & 1) ^ 1];

                    const double2* h2 = (const double2*)hsrc;   // broadcast
                    ull a0 = pack2(xp[u], 0.0f);
                    ull a1 = 0ull, a2 = 0ull, a3 = 0ull;
                    #pragma unroll
                    for (int i = 0; i < 8; i++) {
                        double2 va = h2[2 * i];
                        double2 vb = h2[2 * i + 1];
                        a0 = ffma2(w2[4 * i + 0], __double_as_longlong(va.x), a0);
                        a1 = ffma2(w2[4 * i + 1], __double_as_longlong(va.y), a1);
                        a2 = ffma2(w2[4 * i + 2], __double_as_longlong(vb.x), a2);
                        a3 = ffma2(w2[4 * i + 3], __double_as_longlong(vb.y), a3);
                    }
                    ull tS = fadd2(fadd2(a0, a1), fadd2(a2, a3));
                    float z = lo32(tS) + hi32(tS);
                    float h = tanh_hw(z);

                    hq[u]   = h;
                    hdst[r] = h;
                    __syncthreads();
                }
                *hp = make_float4(hq[0], hq[1], hq[2], hq[3]);  // fire-and-forget
                hp += HID;

                // publish progress every PUB=320 steps (and at chunk ends):
                // the extra barrier orders ALL threads' group STGs before the
                // fence+flag (25 publishes total — negligible cost).
                if (((s + 4) % PUB) == 0) {
                    __syncthreads();
                    if (r == 0) {
                        __threadfence();
                        g_prog[b] = (unsigned)(c * CHUNK + s + 4);
                    }
                }
            }
        }

        // ===== tail: this block computes its own batch's last chunk (ck=24) =====
        {
            const int w    = tid >> 5;       // 0..1
            const int lane = tid & 31;
            const float f0a = fc_w[lane];       const float f0b = fc_w[32 + lane];
            const float f1a = fc_w[64 + lane];  const float f1b = fc_w[96 + lane];
            const float fb0 = fc_b[0];          const float fb1 = fc_b[1];

            const float4* base = (const float4*)(g_h +
                ((size_t)b * GROUPS + (size_t)RCHK * GCHK + (size_t)w * (GCHK / 2)) * HID * 4);

            float num = 0.0f, den = 0.0f;
            readout_groups(base, GCHK / 2, lane, f0a, f0b, f1a, f1b, fb0, fb1, num, den);

            if (lane == 0) { snum2[w] = num; sden2[w] = den; }
            __syncthreads();

            if (tid == 0) {
                float N24 = snum2[0] + snum2[1];
                float D24 = sden2[0] + sden2[1];
                // chunks 0..23 all unblocked during the recurrence (t<=7680)
                while (((volatile unsigned*)g_done)[b] < RCHK) __nanosleep(256);
                __threadfence();
                float N = 0.0f, D = 0.0f;
                #pragma unroll
                for (int i = 0; i < RCHK; i++) {          // fixed order: deterministic
                    N += __ldcg(&g_pnum[b * NCHK2 + i]);
                    D += __ldcg(&g_pden[b * NCHK2 + i]);
                }
                out[b] = __fdividef(N + N24, D + D24);
                g_done[b] = 0u;                           // reset for replay
                g_prog[b] = 0u;
            }
        }
    } else {
        // ================= readout block (chunks 0..23) =================
        __shared__ float snum[8], sden[8];

        const int bk   = bid - BATCH;
        const int ck   = bk / BATCH;             // 0..23, ck-major ordering
        const int b    = bk % BATCH;
        const int w    = tid >> 5;
        const int lane = tid & 31;

        const unsigned need = (unsigned)((ck + 1) * GCHK * 4);   // <= 7680
        if (tid == 0) {
            while (g_prog[b] < need) __nanosleep(1024);
        }
        __syncthreads();
        __threadfence();                         // acquire side

        const float f0a = fc_w[lane];       const float f0b = fc_w[32 + lane];
        const float f1a = fc_w[64 + lane];  const float f1b = fc_w[96 + lane];
        const float fb0 = fc_b[0];          const float fb1 = fc_b[1];

        const float4* base = (const float4*)(g_h +
            ((size_t)b * GROUPS + (size_t)ck * GCHK + (size_t)w * GWARP) * HID * 4);

        float num = 0.0f, den = 0.0f;
        readout_groups(base, GWARP, lane, f0a, f0b, f1a, f1b, fb0, fb1, num, den);

        if (lane == 0) { snum[w] = num; sden[w] = den; }
        __syncthreads();
        if (tid == 0) {
            float N = 0.0f, D = 0.0f;
            #pragma unroll
            for (int i = 0; i < 8; i++) { N += snum[i]; D += sden[i]; }
            g_pnum[b * NCHK2 + ck] = N;
            g_pden[b * NCHK2 + ck] = D;
            __threadfence();                     // release partials before count
            atomicAdd(&g_done[b], 1u);
        }
    }
}

extern "C" void kernel_launch(void* const* d_in, const int* in_sizes, int n_in,
                              void* d_out, int out_size) {
    const float* x    = (const float*)d_in[0];
    const float* W_ih = (const float*)d_in[1];
    const float* b_ih = (const float*)d_in[2];
    const float* W_hh = (const float*)d_in[3];
    const float* b_hh = (const float*)d_in[4];
    const float* fc_w = (const float*)d_in[5];
    const float* fc_b = (const float*)d_in[6];
    float* out = (float*)d_out;
    (void)in_sizes; (void)n_in; (void)out_size;

    rnn_fused<<<BATCH + BATCH * RCHK, 256>>>(x, W_ih, b_ih, W_hh, b_hh, fc_w, fc_b, out);
}

// round 13
// speedup vs baseline: 1.0146x; 1.0146x over previous
#include <cuda_runtime.h>
#include <cuda_fp16.h>

// BasicRNN B=128, S=8000, H=64 — single fused kernel:
//  rec blocks (bid 0..127): recurrence, 64 active threads; stores h=tanh(z) as
//       fp16 (halves scratch traffic vs f32); publishes progress every 320
//       steps at loop boundaries (zero hot-loop overhead). After the loop the
//       SAME block computes its batch's last readout chunk (ck=24) and does
//       the deterministic fixed-order final reduce -> out[b], resetting flags.
//  readout blocks (bid 128..3199): poll progress, process chunks ck=0..23 —
//       all dependencies (t<=7680) publish DURING the recurrence.

#define BATCH 128
#define SEQ   8000
#define HID   64
#define CHUNK 1600
#define NCHUNK (SEQ / CHUNK)
#define PUBS  5                 // publishes per chunk (every 320 steps)
#define PGRP  80                // groups per publish window (320 steps)
#define GROUPS (SEQ / 4)        // 2000 groups of 4 timesteps
#define NCHK2 25                // total partial slots per batch
#define RCHK  24                // chunks handled by readout blocks (0..23)
#define GCHK  (GROUPS / NCHK2)  // 80 groups per chunk (320 steps)
#define GWARP (GCHK / 8)        // 10 groups per warp (readout blocks)

typedef unsigned long long ull;

// h scratch (fp16): [B][GROUPS][HID][4] halves = 131 MB
__device__ __half g_h[(size_t)BATCH * GROUPS * HID * 4];
__device__ float g_pnum[BATCH * NCHK2];
__device__ float g_pden[BATCH * NCHK2];
__device__ volatile unsigned g_prog[BATCH];   // steps completed per batch
__device__ unsigned g_done[BATCH];            // readout chunks completed

__device__ __forceinline__ ull ffma2(ull a, ull b, ull c) {
    ull d;
    asm("fma.rn.f32x2 %0, %1, %2, %3;" : "=l"(d) : "l"(a), "l"(b), "l"(c));
    return d;
}
__device__ __forceinline__ ull fadd2(ull a, ull b) {
    ull d;
    asm("add.rn.f32x2 %0, %1, %2;" : "=l"(d) : "l"(a), "l"(b));
    return d;
}
__device__ __forceinline__ float lo32(ull a) { return __int_as_float((unsigned)a); }
__device__ __forceinline__ float hi32(ull a) { return __int_as_float((unsigned)(a >> 32)); }
__device__ __forceinline__ ull pack2(float lo, float hi) {
    return (ull)__float_as_uint(lo) | ((ull)__float_as_uint(hi) << 32);
}

__device__ __forceinline__ float tanh_hw(float z) {        // MUFU.TANH
    float r;
    asm("tanh.approx.f32 %0, %1;" : "=f"(r) : "f"(z));
    return r;
}
__device__ __forceinline__ float sigmoid_tanh(float x) {   // 1 MUFU
    return fmaf(0.5f, tanh_hw(0.5f * x), 0.5f);
}

// readout inner body over fp16 h: `gcount` groups from base row pointer.
// Each group: row r holds 4 consecutive halves (8 bytes) at base + g*HID.
__device__ __forceinline__ void readout_groups(
    const uint2* base, int gcount, int lane,
    float f0a, float f0b, float f1a, float f1b, float fb0, float fb1,
    float& num, float& den)
{
    #pragma unroll 2
    for (int i = 0; i < gcount; ++i) {
        const uint2* hg = base + (size_t)i * HID;
        uint2 vA = hg[lane];                 // rows 0..31: 4 fp16 steps
        uint2 vB = hg[32 + lane];            // rows 32..63
        float2 A01 = __half22float2(*(const __half2*)&vA.x);
        float2 A23 = __half22float2(*(const __half2*)&vA.y);
        float2 B01 = __half22float2(*(const __half2*)&vB.x);
        float2 B23 = __half22float2(*(const __half2*)&vB.y);
        float p0[4], p1[4];
        p0[0] = fmaf(f0a, A01.x, f0b * B01.x); p1[0] = fmaf(f1a, A01.x, f1b * B01.x);
        p0[1] = fmaf(f0a, A01.y, f0b * B01.y); p1[1] = fmaf(f1a, A01.y, f1b * B01.y);
        p0[2] = fmaf(f0a, A23.x, f0b * B23.x); p1[2] = fmaf(f1a, A23.x, f1b * B23.x);
        p0[3] = fmaf(f0a, A23.y, f0b * B23.y); p1[3] = fmaf(f1a, A23.y, f1b * B23.y);
        #pragma unroll
        for (int o = 16; o > 0; o >>= 1) {
            #pragma unroll
            for (int j = 0; j < 4; j++) {
                p0[j] += __shfl_xor_sync(0xffffffffu, p0[j], o);
                p1[j] += __shfl_xor_sync(0xffffffffu, p1[j], o);
            }
        }
        #pragma unroll
        for (int j = 0; j < 4; j++) {
            float sel = sigmoid_tanh(p0[j] + fb0);
            float sc  = sigmoid_tanh(p1[j] + fb1);
            den += sel;
            num += sc * sel;
        }
    }
}

// ---------------- fused recurrence + overlapped readout + in-kernel finish ----------------
__global__ void __launch_bounds__(256, 1)
rnn_fused(const float* __restrict__ x,      // [B, S]
          const float* __restrict__ W_ih,   // [H, 1]
          const float* __restrict__ b_ih,   // [H]
          const float* __restrict__ W_hh,   // [H, H]
          const float* __restrict__ b_hh,   // [H]
          const float* __restrict__ fc_w,   // [2, H]
          const float* __restrict__ fc_b,   // [2]
          float* __restrict__ out)          // [B]
{
    const int bid = blockIdx.x;
    const int tid = threadIdx.x;

    if (bid < BATCH) {
        // ================= recurrence block =================
        if (tid >= 64) return;           // 64 active threads, 2 warps
        __shared__ __align__(16) float hb[2][HID];
        __shared__ float xs[CHUNK];
        __shared__ float snum2[2], sden2[2];

        const int b = bid;
        const int r = tid;               // row 0..63

        ull w2[32];                      // full W_hh row, packed f32x2
        {
            const double* wp = (const double*)(W_hh + r * HID);
            #pragma unroll
            for (int i = 0; i < 32; i++) w2[i] = __double_as_longlong(wp[i]);
        }
        const float wih_r  = W_ih[r];
        const float bias_r = b_ih[r] + b_hh[r];

        hb[0][r] = 0.0f;   // h_0

        const float* xb = x + (long)b * SEQ;
        uint2* hp = (uint2*)(g_h + (size_t)b * GROUPS * HID * 4) + r;

        __syncthreads();

        unsigned steps_done = 0;
        for (int c = 0; c < NCHUNK; ++c) {
            for (int i = r; i < CHUNK; i += 64)
                xs[i] = xb[c * CHUNK + i];
            __syncthreads();

            #pragma unroll 1
            for (int p = 0; p < PUBS; ++p) {
                const float* xw = xs + p * (PGRP * 4);
                #pragma unroll 1
                for (int g = 0; g < PGRP; ++g) {
                    float xp[4];
                    #pragma unroll
                    for (int u = 0; u < 4; ++u)
                        xp[u] = fmaf(xw[g * 4 + u], wih_r, bias_r);

                    float hq[4];
                    #pragma unroll
                    for (int u = 0; u < 4; ++u) {
                        const float* hsrc = hb[u & 1];
                        float*       hdst = hb[(u & 1) ^ 1];

                        const double2* h2 = (const double2*)hsrc;   // broadcast
                        ull a0 = pack2(xp[u], 0.0f);
                        ull a1 = 0ull, a2 = 0ull, a3 = 0ull;
                        #pragma unroll
                        for (int i = 0; i < 8; i++) {
                            double2 va = h2[2 * i];
                            double2 vb = h2[2 * i + 1];
                            a0 = ffma2(w2[4 * i + 0], __double_as_longlong(va.x), a0);
                            a1 = ffma2(w2[4 * i + 1], __double_as_longlong(va.y), a1);
                            a2 = ffma2(w2[4 * i + 2], __double_as_longlong(vb.x), a2);
                            a3 = ffma2(w2[4 * i + 3], __double_as_longlong(vb.y), a3);
                        }
                        ull tS = fadd2(fadd2(a0, a1), fadd2(a2, a3));
                        float z = lo32(tS) + hi32(tS);
                        float h = tanh_hw(z);

                        hq[u]   = h;
                        hdst[r] = h;
                        __syncthreads();
                    }
                    // pack 4 steps to fp16, one STG.64 (tanh-shadow work)
                    __half2 h01 = __floats2half2_rn(hq[0], hq[1]);
                    __half2 h23 = __floats2half2_rn(hq[2], hq[3]);
                    uint2 pkt;
                    pkt.x = *(unsigned*)&h01;
                    pkt.y = *(unsigned*)&h23;
                    *hp = pkt;
                    hp += HID;
                }
                // publish at window boundary (25 total; last one included)
                steps_done += PGRP * 4;
                __syncthreads();                // order all threads' group STGs
                if (r == 0) {
                    __threadfence();
                    g_prog[b] = steps_done;
                }
            }
        }

        // ===== tail: this block computes its own batch's last chunk (ck=24) =====
        {
            const int w    = tid >> 5;       // 0..1
            const int lane = tid & 31;
            const float f0a = fc_w[lane];       const float f0b = fc_w[32 + lane];
            const float f1a = fc_w[64 + lane];  const float f1b = fc_w[96 + lane];
            const float fb0 = fc_b[0];          const float fb1 = fc_b[1];

            const uint2* base = (const uint2*)(g_h +
                ((size_t)b * GROUPS + (size_t)RCHK * GCHK + (size_t)w * (GCHK / 2)) * HID * 4);

            float num = 0.0f, den = 0.0f;
            readout_groups(base, GCHK / 2, lane, f0a, f0b, f1a, f1b, fb0, fb1, num, den);

            if (lane == 0) { snum2[w] = num; sden2[w] = den; }
            __syncthreads();

            if (tid == 0) {
                float N24 = snum2[0] + snum2[1];
                float D24 = sden2[0] + sden2[1];
                while (((volatile unsigned*)g_done)[b] < RCHK) __nanosleep(256);
                __threadfence();
                float N = 0.0f, D = 0.0f;
                #pragma unroll
                for (int i = 0; i < RCHK; i++) {          // fixed order: deterministic
                    N += __ldcg(&g_pnum[b * NCHK2 + i]);
                    D += __ldcg(&g_pden[b * NCHK2 + i]);
                }
                out[b] = __fdividef(N + N24, D + D24);
                g_done[b] = 0u;                           // reset for replay
                g_prog[b] = 0u;
            }
        }
    } else {
        // ================= readout block (chunks 0..23) =================
        __shared__ float snum[8], sden[8];

        const int bk   = bid - BATCH;
        const int ck   = bk / BATCH;             // 0..23, ck-major ordering
        const int b    = bk % BATCH;
        const int w    = tid >> 5;
        const int lane = tid & 31;

        const unsigned need = (unsigned)((ck + 1) * GCHK * 4);   // <= 7680
        if (tid == 0) {
            while (g_prog[b] < need) __nanosleep(1024);
        }
        __syncthreads();
        __threadfence();                         // acquire side

        const float f0a = fc_w[lane];       const float f0b = fc_w[32 + lane];
        const float f1a = fc_w[64 + lane];  const float f1b = fc_w[96 + lane];
        const float fb0 = fc_b[0];          const float fb1 = fc_b[1];

        const uint2* base = (const uint2*)(g_h +
            ((size_t)b * GROUPS + (size_t)ck * GCHK + (size_t)w * GWARP) * HID * 4);

        float num = 0.0f, den = 0.0f;
        readout_groups(base, GWARP, lane, f0a, f0b, f1a, f1b, fb0, fb1, num, den);

        if (lane == 0) { snum[w] = num; sden[w] = den; }
        __syncthreads();
        if (tid == 0) {
            float N = 0.0f, D = 0.0f;
            #pragma unroll
            for (int i = 0; i < 8; i++) { N += snum[i]; D += sden[i]; }
            g_pnum[b * NCHK2 + ck] = N;
            g_pden[b * NCHK2 + ck] = D;
            __threadfence();                     // release partials before count
            atomicAdd(&g_done[b], 1u);
        }
    }
}

extern "C" void kernel_launch(void* const* d_in, const int* in_sizes, int n_in,
                              void* d_out, int out_size) {
    const float* x    = (const float*)d_in[0];
    const float* W_ih = (const float*)d_in[1];
    const float* b_ih = (const float*)d_in[2];
    const float* W_hh = (const float*)d_in[3];
    const float* b_hh = (const float*)d_in[4];
    const float* fc_w = (const float*)d_in[5];
    const float* fc_b = (const float*)d_in[6];
    float* out = (float*)d_out;
    (void)in_sizes; (void)n_in; (void)out_size;

    rnn_fused<<<BATCH + BATCH * RCHK, 256>>>(x, W_ih, b_ih, W_hh, b_hh, fc_w, fc_b, out);
}

// round 14
// speedup vs baseline: 1.0266x; 1.0118x over previous
#include <cuda_runtime.h>
#include <cuda_fp16.h>

// BasicRNN B=128, S=8000, H=64 — single fused kernel:
//  rec blocks (bid 0..127): recurrence, 64 active threads; h=tanh(z) stored as
//       fp16 with the STG software-pipelined one group behind (issued in the
//       next group's FFMA-issue shadow). Progress published every 320 steps at
//       loop boundaries. After the loop the block computes its batch's last
//       readout chunk (ck=24) and the deterministic final reduce -> out[b].
//  readout blocks (bid 128..3199): poll progress, process chunks ck=0..23 —
//       all dependencies (t<=7680) publish DURING the recurrence.

#define BATCH 128
#define SEQ   8000
#define HID   64
#define CHUNK 1600
#define NCHUNK (SEQ / CHUNK)
#define PUBS  5                 // publishes per chunk (every 320 steps)
#define PGRP  80                // groups per publish window (320 steps)
#define GROUPS (SEQ / 4)        // 2000 groups of 4 timesteps
#define NCHK2 25                // total partial slots per batch
#define RCHK  24                // chunks handled by readout blocks (0..23)
#define GCHK  (GROUPS / NCHK2)  // 80 groups per chunk (320 steps)
#define GWARP (GCHK / 8)        // 10 groups per warp (readout blocks)

typedef unsigned long long ull;

// h scratch (fp16): [B][GROUPS][HID][4] halves = 131 MB
__device__ __half g_h[(size_t)BATCH * GROUPS * HID * 4];
__device__ float g_pnum[BATCH * NCHK2];
__device__ float g_pden[BATCH * NCHK2];
__device__ volatile unsigned g_prog[BATCH];   // steps completed per batch
__device__ unsigned g_done[BATCH];            // readout chunks completed

__device__ __forceinline__ ull ffma2(ull a, ull b, ull c) {
    ull d;
    asm("fma.rn.f32x2 %0, %1, %2, %3;" : "=l"(d) : "l"(a), "l"(b), "l"(c));
    return d;
}
__device__ __forceinline__ ull fadd2(ull a, ull b) {
    ull d;
    asm("add.rn.f32x2 %0, %1, %2;" : "=l"(d) : "l"(a), "l"(b));
    return d;
}
__device__ __forceinline__ float lo32(ull a) { return __int_as_float((unsigned)a); }
__device__ __forceinline__ float hi32(ull a) { return __int_as_float((unsigned)(a >> 32)); }
__device__ __forceinline__ ull pack2(float lo, float hi) {
    return (ull)__float_as_uint(lo) | ((ull)__float_as_uint(hi) << 32);
}

__device__ __forceinline__ float tanh_hw(float z) {        // MUFU.TANH
    float r;
    asm("tanh.approx.f32 %0, %1;" : "=f"(r) : "f"(z));
    return r;
}
__device__ __forceinline__ float sigmoid_tanh(float x) {   // 1 MUFU
    return fmaf(0.5f, tanh_hw(0.5f * x), 0.5f);
}

// readout inner body over fp16 h: `gcount` groups from base row pointer.
__device__ __forceinline__ void readout_groups(
    const uint2* base, int gcount, int lane,
    float f0a, float f0b, float f1a, float f1b, float fb0, float fb1,
    float& num, float& den)
{
    #pragma unroll 2
    for (int i = 0; i < gcount; ++i) {
        const uint2* hg = base + (size_t)i * HID;
        uint2 vA = hg[lane];                 // rows 0..31: 4 fp16 steps
        uint2 vB = hg[32 + lane];            // rows 32..63
        float2 A01 = __half22float2(*(const __half2*)&vA.x);
        float2 A23 = __half22float2(*(const __half2*)&vA.y);
        float2 B01 = __half22float2(*(const __half2*)&vB.x);
        float2 B23 = __half22float2(*(const __half2*)&vB.y);
        float p0[4], p1[4];
        p0[0] = fmaf(f0a, A01.x, f0b * B01.x); p1[0] = fmaf(f1a, A01.x, f1b * B01.x);
        p0[1] = fmaf(f0a, A01.y, f0b * B01.y); p1[1] = fmaf(f1a, A01.y, f1b * B01.y);
        p0[2] = fmaf(f0a, A23.x, f0b * B23.x); p1[2] = fmaf(f1a, A23.x, f1b * B23.x);
        p0[3] = fmaf(f0a, A23.y, f0b * B23.y); p1[3] = fmaf(f1a, A23.y, f1b * B23.y);
        #pragma unroll
        for (int o = 16; o > 0; o >>= 1) {
            #pragma unroll
            for (int j = 0; j < 4; j++) {
                p0[j] += __shfl_xor_sync(0xffffffffu, p0[j], o);
                p1[j] += __shfl_xor_sync(0xffffffffu, p1[j], o);
            }
        }
        #pragma unroll
        for (int j = 0; j < 4; j++) {
            float sel = sigmoid_tanh(p0[j] + fb0);
            float sc  = sigmoid_tanh(p1[j] + fb1);
            den += sel;
            num += sc * sel;
        }
    }
}

// ---------------- fused recurrence + overlapped readout + in-kernel finish ----------------
__global__ void __launch_bounds__(256, 1)
rnn_fused(const float* __restrict__ x,      // [B, S]
          const float* __restrict__ W_ih,   // [H, 1]
          const float* __restrict__ b_ih,   // [H]
          const float* __restrict__ W_hh,   // [H, H]
          const float* __restrict__ b_hh,   // [H]
          const float* __restrict__ fc_w,   // [2, H]
          const float* __restrict__ fc_b,   // [2]
          float* __restrict__ out)          // [B]
{
    const int bid = blockIdx.x;
    const int tid = threadIdx.x;

    if (bid < BATCH) {
        // ================= recurrence block =================
        if (tid >= 64) return;           // 64 active threads, 2 warps
        __shared__ __align__(16) float hb[2][HID];
        __shared__ float xs[CHUNK];
        __shared__ float snum2[2], sden2[2];

        const int b = bid;
        const int r = tid;               // row 0..63

        ull w2[32];                      // full W_hh row, packed f32x2
        {
            const double* wp = (const double*)(W_hh + r * HID);
            #pragma unroll
            for (int i = 0; i < 32; i++) w2[i] = __double_as_longlong(wp[i]);
        }
        const float wih_r  = W_ih[r];
        const float bias_r = b_ih[r] + b_hh[r];

        hb[0][r] = 0.0f;   // h_0

        const float* xb = x + (long)b * SEQ;
        uint2* hp = (uint2*)(g_h + (size_t)b * GROUPS * HID * 4) + r;

        __syncthreads();

        unsigned steps_done = 0;
        uint2 pend;                      // software-pipelined scratch store
        bool  have_pend = false;

        for (int c = 0; c < NCHUNK; ++c) {
            for (int i = r; i < CHUNK; i += 64)
                xs[i] = xb[c * CHUNK + i];
            __syncthreads();

            #pragma unroll 1
            for (int p = 0; p < PUBS; ++p) {
                const float* xw = xs + p * (PGRP * 4);
                #pragma unroll 1
                for (int g = 0; g < PGRP; ++g) {
                    // drain previous group's packed h in this group's issue shadow
                    if (have_pend) {
                        *hp = pend;
                        hp += HID;
                    }
                    have_pend = true;

                    float xp[4];
                    #pragma unroll
                    for (int u = 0; u < 4; ++u)
                        xp[u] = fmaf(xw[g * 4 + u], wih_r, bias_r);

                    unsigned hq16[2];    // fp16-packed results of this group
                    #pragma unroll
                    for (int u = 0; u < 4; u += 2) {
                        float hlo, hhi;
                        #pragma unroll
                        for (int v = 0; v < 2; ++v) {
                            const int uu = u + v;
                            const float* hsrc = hb[uu & 1];
                            float*       hdst = hb[(uu & 1) ^ 1];

                            const double2* h2 = (const double2*)hsrc;  // broadcast
                            ull a0 = pack2(xp[uu], 0.0f);
                            ull a1 = 0ull, a2 = 0ull, a3 = 0ull;
                            #pragma unroll
                            for (int i = 0; i < 8; i++) {
                                double2 va = h2[2 * i];
                                double2 vb = h2[2 * i + 1];
                                a0 = ffma2(w2[4 * i + 0], __double_as_longlong(va.x), a0);
                                a1 = ffma2(w2[4 * i + 1], __double_as_longlong(va.y), a1);
                                a2 = ffma2(w2[4 * i + 2], __double_as_longlong(vb.x), a2);
                                a3 = ffma2(w2[4 * i + 3], __double_as_longlong(vb.y), a3);
                            }
                            ull tS = fadd2(fadd2(a0, a1), fadd2(a2, a3));
                            float z = lo32(tS) + hi32(tS);
                            float h = tanh_hw(z);

                            hdst[r] = h;             // STS first: on the serial path
                            if (v == 0) hlo = h; else hhi = h;
                            __syncthreads();
                        }
                        // cvt in the tail shadow (not between tanh and STS)
                        __half2 hh = __floats2half2_rn(hlo, hhi);
                        hq16[u >> 1] = *(unsigned*)&hh;
                    }
                    pend.x = hq16[0];
                    pend.y = hq16[1];
                }
                // flush pending group, then publish the 320-step window
                if (have_pend) {
                    *hp = pend;
                    hp += HID;
                    have_pend = false;
                }
                steps_done += PGRP * 4;
                __syncthreads();                // order all threads' group STGs
                if (r == 0) {
                    __threadfence();
                    g_prog[b] = steps_done;
                }
            }
        }

        // ===== tail: this block computes its own batch's last chunk (ck=24) =====
        {
            const int w    = tid >> 5;       // 0..1
            const int lane = tid & 31;
            const float f0a = fc_w[lane];       const float f0b = fc_w[32 + lane];
            const float f1a = fc_w[64 + lane];  const float f1b = fc_w[96 + lane];
            const float fb0 = fc_b[0];          const float fb1 = fc_b[1];

            const uint2* base = (const uint2*)(g_h +
                ((size_t)b * GROUPS + (size_t)RCHK * GCHK + (size_t)w * (GCHK / 2)) * HID * 4);

            float num = 0.0f, den = 0.0f;
            readout_groups(base, GCHK / 2, lane, f0a, f0b, f1a, f1b, fb0, fb1, num, den);

            if (lane == 0) { snum2[w] = num; sden2[w] = den; }
            __syncthreads();

            if (tid == 0) {
                float N24 = snum2[0] + snum2[1];
                float D24 = sden2[0] + sden2[1];
                while (((volatile unsigned*)g_done)[b] < RCHK) __nanosleep(256);
                __threadfence();
                float N = 0.0f, D = 0.0f;
                #pragma unroll
                for (int i = 0; i < RCHK; i++) {          // fixed order: deterministic
                    N += __ldcg(&g_pnum[b * NCHK2 + i]);
                    D += __ldcg(&g_pden[b * NCHK2 + i]);
                }
                out[b] = __fdividef(N + N24, D + D24);
                g_done[b] = 0u;                           // reset for replay
                g_prog[b] = 0u;
            }
        }
    } else {
        // ================= readout block (chunks 0..23) =================
        __shared__ float snum[8], sden[8];

        const int bk   = bid - BATCH;
        const int ck   = bk / BATCH;             // 0..23, ck-major ordering
        const int b    = bk % BATCH;
        const int w    = tid >> 5;
        const int lane = tid & 31;

        const unsigned need = (unsigned)((ck + 1) * GCHK * 4);   // <= 7680
        if (tid == 0) {
            while (g_prog[b] < need) __nanosleep(1024);
        }
        __syncthreads();
        __threadfence();                         // acquire side

        const float f0a = fc_w[lane];       const float f0b = fc_w[32 + lane];
        const float f1a = fc_w[64 + lane];  const float f1b = fc_w[96 + lane];
        const float fb0 = fc_b[0];          const float fb1 = fc_b[1];

        const uint2* base = (const uint2*)(g_h +
            ((size_t)b * GROUPS + (size_t)ck * GCHK + (size_t)w * GWARP) * HID * 4);

        float num = 0.0f, den = 0.0f;
        readout_groups(base, GWARP, lane, f0a, f0b, f1a, f1b, fb0, fb1, num, den);

        if (lane == 0) { snum[w] = num; sden[w] = den; }
        __syncthreads();
        if (tid == 0) {
            float N = 0.0f, D = 0.0f;
            #pragma unroll
            for (int i = 0; i < 8; i++) { N += snum[i]; D += sden[i]; }
            g_pnum[b * NCHK2 + ck] = N;
            g_pden[b * NCHK2 + ck] = D;
            __threadfence();                     // release partials before count
            atomicAdd(&g_done[b], 1u);
        }
    }
}

extern "C" void kernel_launch(void* const* d_in, const int* in_sizes, int n_in,
                              void* d_out, int out_size) {
    const float* x    = (const float*)d_in[0];
    const float* W_ih = (const float*)d_in[1];
    const float* b_ih = (const float*)d_in[2];
    const float* W_hh = (const float*)d_in[3];
    const float* b_hh = (const float*)d_in[4];
    const float* fc_w = (const float*)d_in[5];
    const float* fc_b = (const float*)d_in[6];
    float* out = (float*)d_out;
    (void)in_sizes; (void)n_in; (void)out_size;

    rnn_fused<<<BATCH + BATCH * RCHK, 256>>>(x, W_ih, b_ih, W_hh, b_hh, fc_w, fc_b, out);
}